// round 7
// baseline (speedup 1.0000x reference)
#include <cuda_runtime.h>
#include <cstddef>

#define BB 64
#define SS 1024
#define HH 128
#define AA 8
#define WW 5
#define PADW 2
#define CH1 256         // s-rows per K1 block (s-blocked x2 per thread)
#define RSTRIDE 132     // padded smem row stride (floats); conflict-free LDS.128

// Scratch (allocation-free rule: __device__ globals)
__device__ float g_C[AA * WW * HH];        // C[a][w][h]
__device__ float g_logits[BB * AA * SS];   // [b][a][s]

// packed 2xFP32 FMA (FFMA2; PTX-only)
__device__ __forceinline__ void ffma2(unsigned long long& d,
                                      unsigned long long a,
                                      unsigned long long b) {
    asm("fma.rn.f32x2 %0, %1, %2, %0;" : "+l"(d) : "l"(a), "l"(b));
}
__device__ __forceinline__ float f32x2_hsum(unsigned long long v) {
    float lo = __uint_as_float((unsigned)(v & 0xffffffffull));
    float hi = __uint_as_float((unsigned)(v >> 32));
    return lo + hi;
}

// ---------------- Kernel C: combined conv weights ----------------
__global__ void kc_kernel(const float* __restrict__ aspProj,
                          const float* __restrict__ Wt) {
    __shared__ float Wsm[HH * WW];
    int a    = blockIdx.x / 10;
    int part = blockIdx.x % 10;
    for (int i = threadIdx.x; i < HH * WW; i += blockDim.x)
        Wsm[i] = Wt[a * HH * WW + i];
    __syncthreads();

    int rl = threadIdx.x >> 3;
    int fo = threadIdx.x & 7;
    int r  = part * 64 + rl;
    int h  = r / WW, w = r % WW;

    const float4* ap = (const float4*)(aspProj + ((size_t)a * HH + h) * HH + fo * 16);
    float acc = 0.f;
#pragma unroll
    for (int i = 0; i < 4; ++i) {
        float4 x = ap[i];
        int f = fo * 16 + 4 * i;
        acc += x.x * Wsm[(f + 0) * WW + w]
             + x.y * Wsm[(f + 1) * WW + w]
             + x.z * Wsm[(f + 2) * WW + w]
             + x.w * Wsm[(f + 3) * WW + w];
    }
    acc += __shfl_xor_sync(~0u, acc, 1);
    acc += __shfl_xor_sync(~0u, acc, 2);
    acc += __shfl_xor_sync(~0u, acc, 4);
    if (fo == 0)
        g_C[(a * WW + w) * HH + h] = acc;
}

// ---------------- Kernel 1: windowed logits (FFMA2, s-block x2) ----------------
// Each of 128 threads computes logits for s0+t and s0+128+t; every C LDS
// feeds BOTH outputs (per-output LDS drops 12 -> 8 wavefronts).
__global__ void k1_kernel(const float* __restrict__ doc) {
    extern __shared__ float sm[];
    float* rows = sm;                              // (CH1+4) * RSTRIDE
    float* Cbs  = sm + (CH1 + 4) * RSTRIDE;        // 5120

    int b  = blockIdx.y;
    int s0 = blockIdx.x * CH1;
    int t  = threadIdx.x;                          // 128 threads

    for (int i = t; i < AA * WW * HH; i += blockDim.x)
        Cbs[i] = g_C[i];

    // Stage CH1+4 rows (halo 2 each side), zero-padded at edges.
    const int total = (CH1 + 4) * HH;
    for (int idx = t * 4; idx < total; idx += blockDim.x * 4) {
        int r = idx >> 7;
        int c = idx & (HH - 1);
        int gs = s0 - PADW + r;
        float4 v = make_float4(0.f, 0.f, 0.f, 0.f);
        if (gs >= 0 && gs < SS)
            v = *(const float4*)&doc[((size_t)(b * SS + gs)) * HH + c];
        *(float4*)&rows[r * RSTRIDE + c] = v;
    }
    __syncthreads();

    unsigned long long acc2[2 * AA];
#pragma unroll
    for (int a = 0; a < 2 * AA; ++a) acc2[a] = 0ull;

#pragma unroll
    for (int w = 0; w < WW; ++w) {
        const ulonglong2* rpA = (const ulonglong2*)(rows + (t + w) * RSTRIDE);
        const ulonglong2* rpB = (const ulonglong2*)(rows + (t + 128 + w) * RSTRIDE);
#pragma unroll 4
        for (int h4 = 0; h4 < HH / 4; ++h4) {
            ulonglong2 xA = rpA[h4];
            ulonglong2 xB = rpB[h4];
#pragma unroll
            for (int a = 0; a < AA; ++a) {
                ulonglong2 c = *(const ulonglong2*)&Cbs[(a * WW + w) * HH + 4 * h4];
                ffma2(acc2[a],      xA.x, c.x);
                ffma2(acc2[a],      xA.y, c.y);
                ffma2(acc2[AA + a], xB.x, c.x);
                ffma2(acc2[AA + a], xB.y, c.y);
            }
        }
    }

#pragma unroll
    for (int a = 0; a < AA; ++a) {
        g_logits[((size_t)b * AA + a) * SS + s0 + t]       = f32x2_hsum(acc2[a]);
        g_logits[((size_t)b * AA + a) * SS + s0 + 128 + t] = f32x2_hsum(acc2[AA + a]);
    }
}

// ---------------- Kernel 2: softmax + T + rep (4 aspects/block, R5-proven) ----------------
#define AH 4   // aspects per block
__global__ void __launch_bounds__(1024, 1)
k2_kernel(const float* __restrict__ doc,
          const float* __restrict__ aspProj,
          float* __restrict__ out) {
    __shared__ __align__(16) float buf[AH * SS];   // 16KB: attn, then P[8][512], then rep_part
    __shared__ float T_sm[AH * HH];                // 2KB
    __shared__ float red[32];
    __shared__ float redA[AH];

    int b    = blockIdx.x;
    int a_lo = blockIdx.y * AH;
    int tid  = threadIdx.x;
    int lane = tid & 31;
    int warp = tid >> 5;

    // ---- Phase A: 4 concurrent softmaxes (256 threads per aspect) ----
    {
        int ga = tid >> 8;       // local aspect 0..3
        int gs = tid & 255;
        float v[4], e[4];
        const float* lg = g_logits + ((size_t)b * AA + a_lo + ga) * SS + gs;
#pragma unroll
        for (int k = 0; k < 4; ++k) v[k] = lg[256 * k];

        float m = fmaxf(fmaxf(v[0], v[1]), fmaxf(v[2], v[3]));
#pragma unroll
        for (int o = 16; o; o >>= 1) m = fmaxf(m, __shfl_xor_sync(~0u, m, o));
        if (lane == 0) red[warp] = m;
        __syncthreads();
        if (warp == 0) {
            float x = red[lane];
            x = fmaxf(x, __shfl_xor_sync(~0u, x, 1));
            x = fmaxf(x, __shfl_xor_sync(~0u, x, 2));
            x = fmaxf(x, __shfl_xor_sync(~0u, x, 4));
            if ((lane & 7) == 0) redA[lane >> 3] = x;
        }
        __syncthreads();
        m = redA[ga];

        float s = 0.f;
#pragma unroll
        for (int k = 0; k < 4; ++k) { e[k] = __expf(v[k] - m); s += e[k]; }
#pragma unroll
        for (int o = 16; o; o >>= 1) s += __shfl_xor_sync(~0u, s, o);
        if (lane == 0) red[warp] = s;
        __syncthreads();
        if (warp == 0) {
            float x = red[lane];
            x += __shfl_xor_sync(~0u, x, 1);
            x += __shfl_xor_sync(~0u, x, 2);
            x += __shfl_xor_sync(~0u, x, 4);
            if ((lane & 7) == 0) redA[lane >> 3] = x;
        }
        __syncthreads();
        float inv = 1.f / redA[ga];

        float* osm = buf + ga * SS + gs;
        float* og  = out + ((size_t)b * AA + a_lo + ga) * SS + gs;
#pragma unroll
        for (int k = 0; k < 4; ++k) {
            float at = e[k] * inv;
            osm[256 * k] = at;
            og[256 * k]  = at;
        }
    }
    __syncthreads();

    // ---- Phase B: T[a][h] = sum_s doc[b,s,h] * attn[a][s] ----
    float tp[AH * 4];
#pragma unroll
    for (int i = 0; i < AH * 4; ++i) tp[i] = 0.f;

    const float* dbase = doc + (size_t)b * SS * HH + 4 * lane;
#pragma unroll 4
    for (int it = 0; it < SS / 32; ++it) {
        int s = warp + it * 32;
        float4 x = *(const float4*)&dbase[(size_t)s * HH];
#pragma unroll
        for (int a = 0; a < AH; ++a) {
            float aw = buf[a * SS + s];          // broadcast
            tp[a * 4 + 0] += aw * x.x;
            tp[a * 4 + 1] += aw * x.y;
            tp[a * 4 + 2] += aw * x.z;
            tp[a * 4 + 3] += aw * x.w;
        }
    }
    __syncthreads();   // attn region dead -> reuse buf as P[8][AH*HH]

    // staged (atomic-free) reduction over 32 warps into 8 slot buffers
    float* P = buf;
#pragma unroll
    for (int r = 0; r < 4; ++r) {
        if ((warp >> 3) == r) {
            float* dst = P + (warp & 7) * (AH * HH);
#pragma unroll
            for (int a = 0; a < AH; ++a) {
                float4* d4 = (float4*)&dst[a * HH + 4 * lane];
                float4 v = make_float4(tp[a*4+0], tp[a*4+1], tp[a*4+2], tp[a*4+3]);
                if (r == 0) *d4 = v;
                else {
                    float4 o = *d4;
                    o.x += v.x; o.y += v.y; o.z += v.z; o.w += v.w;
                    *d4 = o;
                }
            }
        }
        __syncthreads();
    }
    if (tid < AH * HH / 4) {
        const float4* P4 = (const float4*)P;
        float4 r = make_float4(0.f, 0.f, 0.f, 0.f);
#pragma unroll
        for (int sl = 0; sl < 8; ++sl) {
            float4 p = P4[sl * (AH * HH / 4) + tid];
            r.x += p.x; r.y += p.y; r.z += p.z; r.w += p.w;
        }
        *(float4*)&T_sm[4 * tid] = r;
    }
    __syncthreads();

    // ---- Phase C: rep[a][ho] = sum_h T[a][h] * aspProj[a_g][h][ho] ----
    {
        int a   = tid >> 8;          // local aspect 0..3
        int hq  = (tid >> 5) & 7;    // h-octant (16 h each)
        int ho4 = tid & 31;
        const float* apB = aspProj + (size_t)(a_lo + a) * HH * HH;
        float4 acc = make_float4(0.f, 0.f, 0.f, 0.f);
#pragma unroll
        for (int i = 0; i < 16; ++i) {
            int h = hq * 16 + i;
            float tv = T_sm[a * HH + h];
            float4 c = *(const float4*)&apB[(size_t)h * HH + 4 * ho4];
            acc.x += tv * c.x;
            acc.y += tv * c.y;
            acc.z += tv * c.z;
            acc.w += tv * c.w;
        }
        float* rep_part = buf;       // P dead
        __syncthreads();
        *(float4*)&rep_part[tid * 4] = acc;
        __syncthreads();

        if (tid < AH * 32) {
            int a2 = tid >> 5;
            int hb = tid & 31;
            float4 r = make_float4(0.f, 0.f, 0.f, 0.f);
#pragma unroll
            for (int hq2 = 0; hq2 < 8; ++hq2) {
                float4 p = *(const float4*)&rep_part[(((a2 * 8 + hq2) * 32) + hb) * 4];
                r.x += p.x; r.y += p.y; r.z += p.z; r.w += p.w;
            }
            size_t off = (size_t)BB * AA * SS
                       + ((size_t)b * AA + a_lo + a2) * HH + 4 * hb;
            *(float4*)&out[off] = r;
        }
    }
}

extern "C" void kernel_launch(void* const* d_in, const int* in_sizes, int n_in,
                              void* d_out, int out_size) {
    const float* doc     = (const float*)d_in[0];  // (64,1024,128) f32
    const float* Wt      = (const float*)d_in[1];  // (8, 640) f32
    const float* aspProj = (const float*)d_in[2];  // (8,128,128) f32
    float* out = (float*)d_out;

    kc_kernel<<<80, 512>>>(aspProj, Wt);

    size_t sm1 = ((size_t)(CH1 + 4) * RSTRIDE + (size_t)AA * WW * HH) * sizeof(float);
    cudaFuncSetAttribute(k1_kernel, cudaFuncAttributeMaxDynamicSharedMemorySize, (int)sm1);
    k1_kernel<<<dim3(SS / CH1, BB), 128, sm1>>>(doc);

    k2_kernel<<<dim3(BB, 2), 1024>>>(doc, aspProj, out);
}

// round 8
// speedup vs baseline: 1.1010x; 1.1010x over previous
#include <cuda_runtime.h>
#include <cstddef>

#define BB 64
#define SS 1024
#define HH 128
#define AA 8
#define WW 5
#define PADW 2
#define CH 128          // s-rows per K1 block
#define RSTRIDE 132     // padded smem row stride (floats); conflict-free LDS.128

// Scratch (allocation-free rule: __device__ globals)
__device__ float g_C[AA * WW * HH];        // C[a][w][h]
__device__ float g_logits[BB * AA * SS];   // [b][a][s]

// packed 2xFP32 FMA (FFMA2; PTX-only)
__device__ __forceinline__ void ffma2(unsigned long long& d,
                                      unsigned long long a,
                                      unsigned long long b) {
    asm("fma.rn.f32x2 %0, %1, %2, %0;" : "+l"(d) : "l"(a), "l"(b));
}
__device__ __forceinline__ float f32x2_hsum(unsigned long long v) {
    float lo = __uint_as_float((unsigned)(v & 0xffffffffull));
    float hi = __uint_as_float((unsigned)(v >> 32));
    return lo + hi;
}
__device__ __forceinline__ unsigned long long dup_f32(float a) {
    unsigned long long r;
    asm("mov.b64 %0, {%1, %1};" : "=l"(r) : "f"(a));
    return r;
}

// ---------------- Kernel C: combined conv weights (R5, unchanged) ----------------
__global__ void kc_kernel(const float* __restrict__ aspProj,
                          const float* __restrict__ Wt) {
    __shared__ float Wsm[HH * WW];
    int a    = blockIdx.x / 10;
    int part = blockIdx.x % 10;
    for (int i = threadIdx.x; i < HH * WW; i += blockDim.x)
        Wsm[i] = Wt[a * HH * WW + i];
    __syncthreads();

    int rl = threadIdx.x >> 3;
    int fo = threadIdx.x & 7;
    int r  = part * 64 + rl;
    int h  = r / WW, w = r % WW;

    const float4* ap = (const float4*)(aspProj + ((size_t)a * HH + h) * HH + fo * 16);
    float acc = 0.f;
#pragma unroll
    for (int i = 0; i < 4; ++i) {
        float4 x = ap[i];
        int f = fo * 16 + 4 * i;
        acc += x.x * Wsm[(f + 0) * WW + w]
             + x.y * Wsm[(f + 1) * WW + w]
             + x.z * Wsm[(f + 2) * WW + w]
             + x.w * Wsm[(f + 3) * WW + w];
    }
    acc += __shfl_xor_sync(~0u, acc, 1);
    acc += __shfl_xor_sync(~0u, acc, 2);
    acc += __shfl_xor_sync(~0u, acc, 4);
    if (fo == 0)
        g_C[(a * WW + w) * HH + h] = acc;
}

// ---------------- Kernel 1: windowed logits (R5, unchanged: CH=128, 2 CTA/SM) ----------------
__global__ void k1_kernel(const float* __restrict__ doc) {
    extern __shared__ float sm[];
    float* rows = sm;                              // (CH+4) * RSTRIDE
    float* Cbs  = sm + (CH + 4) * RSTRIDE;         // 5120

    int b  = blockIdx.y;
    int s0 = blockIdx.x * CH;
    int t  = threadIdx.x;

    for (int i = t; i < AA * WW * HH; i += blockDim.x)
        Cbs[i] = g_C[i];

    const int total = (CH + 4) * HH;
    for (int idx = t * 4; idx < total; idx += blockDim.x * 4) {
        int r = idx >> 7;
        int c = idx & (HH - 1);
        int gs = s0 - PADW + r;
        float4 v = make_float4(0.f, 0.f, 0.f, 0.f);
        if (gs >= 0 && gs < SS)
            v = *(const float4*)&doc[((size_t)(b * SS + gs)) * HH + c];
        *(float4*)&rows[r * RSTRIDE + c] = v;
    }
    __syncthreads();

    unsigned long long acc2[AA];
#pragma unroll
    for (int a = 0; a < AA; ++a) acc2[a] = 0ull;

#pragma unroll
    for (int w = 0; w < WW; ++w) {
        const ulonglong2* rp = (const ulonglong2*)(rows + (t + w) * RSTRIDE);
#pragma unroll 4
        for (int h4 = 0; h4 < HH / 4; ++h4) {
            ulonglong2 x = rp[h4];
#pragma unroll
            for (int a = 0; a < AA; ++a) {
                ulonglong2 c = *(const ulonglong2*)&Cbs[(a * WW + w) * HH + 4 * h4];
                ffma2(acc2[a], x.x, c.x);
                ffma2(acc2[a], x.y, c.y);
            }
        }
    }

    int s = s0 + t;
#pragma unroll
    for (int a = 0; a < AA; ++a)
        g_logits[((size_t)b * AA + a) * SS + s] = f32x2_hsum(acc2[a]);
}

// ---------------- Kernel 2: softmax + T + rep (AH=8, 64 blocks, NO PDL) ----------------
__global__ void __launch_bounds__(1024, 1)
k2_kernel(const float* __restrict__ doc,
          const float* __restrict__ aspProj,
          float* __restrict__ out) {
    extern __shared__ __align__(16) float sm2[];
    float* attn = sm2;                 // AA*SS = 8192 floats (32KB)
    float* P    = sm2 + AA * SS;       // 8 slots x AA*HH = 8192 floats (32KB)
    __shared__ float T_sm[AA * HH];    // 4KB
    __shared__ float red[32];
    __shared__ float redA[AA];

    int b    = blockIdx.x;
    int tid  = threadIdx.x;
    int lane = tid & 31;
    int warp = tid >> 5;
    int ga   = tid >> 7;     // aspect 0..7 (4 warps each)
    int gs   = tid & 127;

    // ---- Phase A: 8 concurrent softmaxes ----
    {
        float v[8], e[8];
        const float* lg = g_logits + ((size_t)b * AA + ga) * SS + gs;
#pragma unroll
        for (int k = 0; k < 8; ++k) v[k] = lg[128 * k];

        float m = v[0];
#pragma unroll
        for (int k = 1; k < 8; ++k) m = fmaxf(m, v[k]);
#pragma unroll
        for (int o = 16; o; o >>= 1) m = fmaxf(m, __shfl_xor_sync(~0u, m, o));
        if (lane == 0) red[warp] = m;
        __syncthreads();
        if (warp == 0) {
            float x = red[lane];
            x = fmaxf(x, __shfl_xor_sync(~0u, x, 1));
            x = fmaxf(x, __shfl_xor_sync(~0u, x, 2));
            if ((lane & 3) == 0) redA[lane >> 2] = x;
        }
        __syncthreads();
        m = redA[ga];

        float s = 0.f;
#pragma unroll
        for (int k = 0; k < 8; ++k) { e[k] = __expf(v[k] - m); s += e[k]; }
#pragma unroll
        for (int o = 16; o; o >>= 1) s += __shfl_xor_sync(~0u, s, o);
        if (lane == 0) red[warp] = s;
        __syncthreads();
        if (warp == 0) {
            float x = red[lane];
            x += __shfl_xor_sync(~0u, x, 1);
            x += __shfl_xor_sync(~0u, x, 2);
            if ((lane & 3) == 0) redA[lane >> 2] = x;
        }
        __syncthreads();
        float inv = 1.f / redA[ga];

        float* osm = attn + ga * SS + gs;
        float* og  = out + ((size_t)b * AA + ga) * SS + gs;
#pragma unroll
        for (int k = 0; k < 8; ++k) {
            float at = e[k] * inv;
            osm[128 * k] = at;
            og[128 * k]  = at;
        }
    }
    __syncthreads();

    // ---- Phase B: T[a][h] = sum_s doc[b,s,h] * attn[a][s]  (FFMA2, doc read ONCE) ----
    unsigned long long tp2[AA * 2];
#pragma unroll
    for (int i = 0; i < AA * 2; ++i) tp2[i] = 0ull;

    const float* dbase = doc + (size_t)b * SS * HH + 4 * lane;
#pragma unroll 4
    for (int it = 0; it < SS / 32; ++it) {
        int s = warp + it * 32;
        ulonglong2 x = *(const ulonglong2*)&dbase[(size_t)s * HH];
#pragma unroll
        for (int a = 0; a < AA; ++a) {
            unsigned long long aw2 = dup_f32(attn[a * SS + s]);
            ffma2(tp2[2 * a + 0], x.x, aw2);
            ffma2(tp2[2 * a + 1], x.y, aw2);
        }
    }
    __syncthreads();   // attn reads done

    // staged (atomic-free) reduction: 32 warps -> 8 slot buffers -> T
#pragma unroll
    for (int r = 0; r < 4; ++r) {
        if ((warp >> 3) == r) {
            float* dst = P + (warp & 7) * (AA * HH);
#pragma unroll
            for (int a = 0; a < AA; ++a) {
                float4* d4 = (float4*)&dst[a * HH + 4 * lane];
                float4 v = *reinterpret_cast<float4*>(&tp2[2 * a]);
                if (r == 0) *d4 = v;
                else {
                    float4 o = *d4;
                    o.x += v.x; o.y += v.y; o.z += v.z; o.w += v.w;
                    *d4 = o;
                }
            }
        }
        __syncthreads();
    }
    if (tid < AA * HH / 4) {
        const float4* P4 = (const float4*)P;
        float4 r = make_float4(0.f, 0.f, 0.f, 0.f);
#pragma unroll
        for (int sl = 0; sl < 8; ++sl) {
            float4 p = P4[sl * (AA * HH / 4) + tid];
            r.x += p.x; r.y += p.y; r.z += p.z; r.w += p.w;
        }
        *(float4*)&T_sm[4 * tid] = r;
    }
    __syncthreads();

    // ---- Phase C: rep[a][ho] = sum_h T[a][h] * aspProj[a][h][ho] ----
    {
        int a   = tid >> 7;
        int hq  = (tid >> 5) & 3;
        int ho4 = tid & 31;
        const float* apB = aspProj + (size_t)a * HH * HH;
        float4 acc = make_float4(0.f, 0.f, 0.f, 0.f);
#pragma unroll 4
        for (int i = 0; i < 32; ++i) {
            int h = hq * 32 + i;
            float tv = T_sm[a * HH + h];
            float4 c = *(const float4*)&apB[(size_t)h * HH + 4 * ho4];
            acc.x += tv * c.x;
            acc.y += tv * c.y;
            acc.z += tv * c.z;
            acc.w += tv * c.w;
        }
        float* rep_part = attn;      // attn dead
        *(float4*)&rep_part[tid * 4] = acc;
        __syncthreads();

        if (tid < AA * 32) {
            int a2 = tid >> 5;
            int hb = tid & 31;
            float4 r = make_float4(0.f, 0.f, 0.f, 0.f);
#pragma unroll
            for (int hq2 = 0; hq2 < 4; ++hq2) {
                float4 p = *(const float4*)&rep_part[(((a2 * 4 + hq2) * 32) + hb) * 4];
                r.x += p.x; r.y += p.y; r.z += p.z; r.w += p.w;
            }
            size_t off = (size_t)BB * AA * SS + ((size_t)b * AA + a2) * HH + 4 * hb;
            *(float4*)&out[off] = r;
        }
    }
}

extern "C" void kernel_launch(void* const* d_in, const int* in_sizes, int n_in,
                              void* d_out, int out_size) {
    const float* doc     = (const float*)d_in[0];  // (64,1024,128) f32
    const float* Wt      = (const float*)d_in[1];  // (8, 640) f32
    const float* aspProj = (const float*)d_in[2];  // (8,128,128) f32
    float* out = (float*)d_out;

    kc_kernel<<<80, 512>>>(aspProj, Wt);

    size_t sm1 = ((size_t)(CH + 4) * RSTRIDE + (size_t)AA * WW * HH) * sizeof(float);
    cudaFuncSetAttribute(k1_kernel, cudaFuncAttributeMaxDynamicSharedMemorySize, (int)sm1);
    k1_kernel<<<dim3(SS / CH, BB), CH, sm1>>>(doc);

    size_t sm2 = (size_t)(2 * AA * SS) * sizeof(float);   // 64KB
    cudaFuncSetAttribute(k2_kernel, cudaFuncAttributeMaxDynamicSharedMemorySize, (int)sm2);
    k2_kernel<<<BB, 1024, sm2>>>(doc, aspProj, out);
}

// round 9
// speedup vs baseline: 1.3282x; 1.2063x over previous
#include <cuda_runtime.h>
#include <cstddef>

#define BB 64
#define SS 1024
#define HH 128
#define AA 8
#define WW 5
#define PADW 2
#define CH2 256         // s-rows per K1 block (k=2 s-block, h-split-2)
#define RSTRIDE 132     // padded smem row stride (floats); conflict-free LDS.128

// Scratch (allocation-free rule: __device__ globals)
__device__ float g_C[AA * WW * HH];        // C[a][w][h]
__device__ float g_logits[BB * AA * SS];   // [b][a][s]

// packed 2xFP32 FMA (FFMA2; PTX-only)
__device__ __forceinline__ void ffma2(unsigned long long& d,
                                      unsigned long long a,
                                      unsigned long long b) {
    asm("fma.rn.f32x2 %0, %1, %2, %0;" : "+l"(d) : "l"(a), "l"(b));
}
__device__ __forceinline__ float f32x2_hsum(unsigned long long v) {
    float lo = __uint_as_float((unsigned)(v & 0xffffffffull));
    float hi = __uint_as_float((unsigned)(v >> 32));
    return lo + hi;
}

// ---------------- Kernel C: combined conv weights (R5, unchanged) ----------------
__global__ void kc_kernel(const float* __restrict__ aspProj,
                          const float* __restrict__ Wt) {
    __shared__ float Wsm[HH * WW];
    int a    = blockIdx.x / 10;
    int part = blockIdx.x % 10;
    for (int i = threadIdx.x; i < HH * WW; i += blockDim.x)
        Wsm[i] = Wt[a * HH * WW + i];
    __syncthreads();

    int rl = threadIdx.x >> 3;
    int fo = threadIdx.x & 7;
    int r  = part * 64 + rl;
    int h  = r / WW, w = r % WW;

    const float4* ap = (const float4*)(aspProj + ((size_t)a * HH + h) * HH + fo * 16);
    float acc = 0.f;
#pragma unroll
    for (int i = 0; i < 4; ++i) {
        float4 x = ap[i];
        int f = fo * 16 + 4 * i;
        acc += x.x * Wsm[(f + 0) * WW + w]
             + x.y * Wsm[(f + 1) * WW + w]
             + x.z * Wsm[(f + 2) * WW + w]
             + x.w * Wsm[(f + 3) * WW + w];
    }
    acc += __shfl_xor_sync(~0u, acc, 1);
    acc += __shfl_xor_sync(~0u, acc, 2);
    acc += __shfl_xor_sync(~0u, acc, 4);
    if (fo == 0)
        g_C[(a * WW + w) * HH + h] = acc;
}

// ---------------- Kernel 1: windowed logits (k=2 s-block, h-split-2, 8 warps) ----------------
// 256 threads: hg = tid>>7 owns h-half [hg*64, hg*64+64); ts = tid&127 owns
// s0+ts and s0+128+ts. Every C broadcast feeds 2 s-outputs -> 40 wavefronts/s
// (was 60). Cross-half reduction via 2KB smem buffer.
__global__ void k1_kernel(const float* __restrict__ doc) {
    extern __shared__ float sm[];
    float* rows = sm;                              // (CH2+4) * RSTRIDE = 34320
    float* Cbs  = rows + (CH2 + 4) * RSTRIDE;      // 5120
    float* redb = Cbs + AA * WW * HH;              // AA*CH2 = 2048

    int b   = blockIdx.y;
    int s0  = blockIdx.x * CH2;
    int tid = threadIdx.x;                         // 0..255
    int hg  = tid >> 7;                            // h-half
    int ts  = tid & 127;                           // s slot

    for (int i = tid; i < AA * WW * HH; i += 256)
        Cbs[i] = g_C[i];

    // Stage CH2+4 rows (halo 2 each side), zero-padded at edges.
    const int total = (CH2 + 4) * HH;              // 33280
    for (int idx = tid * 4; idx < total; idx += 256 * 4) {
        int r = idx >> 7;
        int c = idx & (HH - 1);
        int gs = s0 - PADW + r;
        float4 v = make_float4(0.f, 0.f, 0.f, 0.f);
        if (gs >= 0 && gs < SS)
            v = *(const float4*)&doc[((size_t)(b * SS + gs)) * HH + c];
        *(float4*)&rows[r * RSTRIDE + c] = v;
    }
    __syncthreads();

    unsigned long long accA[AA], accB[AA];
#pragma unroll
    for (int a = 0; a < AA; ++a) { accA[a] = 0ull; accB[a] = 0ull; }

    const int hoff = hg * 64;
#pragma unroll
    for (int w = 0; w < WW; ++w) {
        const ulonglong2* rpA = (const ulonglong2*)(rows + (ts + w) * RSTRIDE + hoff);
        const ulonglong2* rpB = (const ulonglong2*)(rows + (ts + 128 + w) * RSTRIDE + hoff);
#pragma unroll 4
        for (int h4 = 0; h4 < 16; ++h4) {          // 16 x float4 = 64 h
            ulonglong2 xA = rpA[h4];
            ulonglong2 xB = rpB[h4];
#pragma unroll
            for (int a = 0; a < AA; ++a) {
                ulonglong2 c = *(const ulonglong2*)&Cbs[(a * WW + w) * HH + hoff + 4 * h4];
                ffma2(accA[a], xA.x, c.x);
                ffma2(accA[a], xA.y, c.y);
                ffma2(accB[a], xB.x, c.x);
                ffma2(accB[a], xB.y, c.y);
            }
        }
    }

    // cross-half reduction: half 1 publishes, half 0 combines + stores
    if (hg == 1) {
#pragma unroll
        for (int a = 0; a < AA; ++a) {
            redb[a * CH2 + ts]       = f32x2_hsum(accA[a]);
            redb[a * CH2 + 128 + ts] = f32x2_hsum(accB[a]);
        }
    }
    __syncthreads();
    if (hg == 0) {
#pragma unroll
        for (int a = 0; a < AA; ++a) {
            float* lg = g_logits + ((size_t)b * AA + a) * SS + s0;
            lg[ts]       = f32x2_hsum(accA[a]) + redb[a * CH2 + ts];
            lg[128 + ts] = f32x2_hsum(accB[a]) + redb[a * CH2 + 128 + ts];
        }
    }
}

// ---------------- Kernel 2: softmax + T + rep (R5-proven: AH=4, 128 blocks) ----------------
#define AH 4   // aspects per block
__global__ void __launch_bounds__(1024, 1)
k2_kernel(const float* __restrict__ doc,
          const float* __restrict__ aspProj,
          float* __restrict__ out) {
    __shared__ __align__(16) float buf[AH * SS];   // 16KB: attn, then P[8][512], then rep_part
    __shared__ float T_sm[AH * HH];                // 2KB
    __shared__ float red[32];
    __shared__ float redA[AH];

    int b    = blockIdx.x;
    int a_lo = blockIdx.y * AH;
    int tid  = threadIdx.x;
    int lane = tid & 31;
    int warp = tid >> 5;

    // ---- Phase A: 4 concurrent softmaxes (256 threads per aspect) ----
    {
        int ga = tid >> 8;       // local aspect 0..3
        int gs = tid & 255;
        float v[4], e[4];
        const float* lg = g_logits + ((size_t)b * AA + a_lo + ga) * SS + gs;
#pragma unroll
        for (int k = 0; k < 4; ++k) v[k] = lg[256 * k];

        float m = fmaxf(fmaxf(v[0], v[1]), fmaxf(v[2], v[3]));
#pragma unroll
        for (int o = 16; o; o >>= 1) m = fmaxf(m, __shfl_xor_sync(~0u, m, o));
        if (lane == 0) red[warp] = m;
        __syncthreads();
        if (warp == 0) {
            float x = red[lane];
            x = fmaxf(x, __shfl_xor_sync(~0u, x, 1));
            x = fmaxf(x, __shfl_xor_sync(~0u, x, 2));
            x = fmaxf(x, __shfl_xor_sync(~0u, x, 4));
            if ((lane & 7) == 0) redA[lane >> 3] = x;
        }
        __syncthreads();
        m = redA[ga];

        float s = 0.f;
#pragma unroll
        for (int k = 0; k < 4; ++k) { e[k] = __expf(v[k] - m); s += e[k]; }
#pragma unroll
        for (int o = 16; o; o >>= 1) s += __shfl_xor_sync(~0u, s, o);
        if (lane == 0) red[warp] = s;
        __syncthreads();
        if (warp == 0) {
            float x = red[lane];
            x += __shfl_xor_sync(~0u, x, 1);
            x += __shfl_xor_sync(~0u, x, 2);
            x += __shfl_xor_sync(~0u, x, 4);
            if ((lane & 7) == 0) redA[lane >> 3] = x;
        }
        __syncthreads();
        float inv = 1.f / redA[ga];

        float* osm = buf + ga * SS + gs;
        float* og  = out + ((size_t)b * AA + a_lo + ga) * SS + gs;
#pragma unroll
        for (int k = 0; k < 4; ++k) {
            float at = e[k] * inv;
            osm[256 * k] = at;
            og[256 * k]  = at;
        }
    }
    __syncthreads();

    // ---- Phase B: T[a][h] = sum_s doc[b,s,h] * attn[a][s] ----
    float tp[AH * 4];
#pragma unroll
    for (int i = 0; i < AH * 4; ++i) tp[i] = 0.f;

    const float* dbase = doc + (size_t)b * SS * HH + 4 * lane;
#pragma unroll 4
    for (int it = 0; it < SS / 32; ++it) {
        int s = warp + it * 32;
        float4 x = *(const float4*)&dbase[(size_t)s * HH];
#pragma unroll
        for (int a = 0; a < AH; ++a) {
            float aw = buf[a * SS + s];          // broadcast
            tp[a * 4 + 0] += aw * x.x;
            tp[a * 4 + 1] += aw * x.y;
            tp[a * 4 + 2] += aw * x.z;
            tp[a * 4 + 3] += aw * x.w;
        }
    }
    __syncthreads();   // attn region dead -> reuse buf as P[8][AH*HH]

    // staged (atomic-free) reduction over 32 warps into 8 slot buffers
    float* P = buf;
#pragma unroll
    for (int r = 0; r < 4; ++r) {
        if ((warp >> 3) == r) {
            float* dst = P + (warp & 7) * (AH * HH);
#pragma unroll
            for (int a = 0; a < AH; ++a) {
                float4* d4 = (float4*)&dst[a * HH + 4 * lane];
                float4 v = make_float4(tp[a*4+0], tp[a*4+1], tp[a*4+2], tp[a*4+3]);
                if (r == 0) *d4 = v;
                else {
                    float4 o = *d4;
                    o.x += v.x; o.y += v.y; o.z += v.z; o.w += v.w;
                    *d4 = o;
                }
            }
        }
        __syncthreads();
    }
    if (tid < AH * HH / 4) {
        const float4* P4 = (const float4*)P;
        float4 r = make_float4(0.f, 0.f, 0.f, 0.f);
#pragma unroll
        for (int sl = 0; sl < 8; ++sl) {
            float4 p = P4[sl * (AH * HH / 4) + tid];
            r.x += p.x; r.y += p.y; r.z += p.z; r.w += p.w;
        }
        *(float4*)&T_sm[4 * tid] = r;
    }
    __syncthreads();

    // ---- Phase C: rep[a][ho] = sum_h T[a][h] * aspProj[a_g][h][ho] ----
    {
        int a   = tid >> 8;          // local aspect 0..3
        int hq  = (tid >> 5) & 7;    // h-octant (16 h each)
        int ho4 = tid & 31;
        const float* apB = aspProj + (size_t)(a_lo + a) * HH * HH;
        float4 acc = make_float4(0.f, 0.f, 0.f, 0.f);
#pragma unroll
        for (int i = 0; i < 16; ++i) {
            int h = hq * 16 + i;
            float tv = T_sm[a * HH + h];
            float4 c = *(const float4*)&apB[(size_t)h * HH + 4 * ho4];
            acc.x += tv * c.x;
            acc.y += tv * c.y;
            acc.z += tv * c.z;
            acc.w += tv * c.w;
        }
        float* rep_part = buf;       // P dead
        __syncthreads();
        *(float4*)&rep_part[tid * 4] = acc;
        __syncthreads();

        if (tid < AH * 32) {
            int a2 = tid >> 5;
            int hb = tid & 31;
            float4 r = make_float4(0.f, 0.f, 0.f, 0.f);
#pragma unroll
            for (int hq2 = 0; hq2 < 8; ++hq2) {
                float4 p = *(const float4*)&rep_part[(((a2 * 8 + hq2) * 32) + hb) * 4];
                r.x += p.x; r.y += p.y; r.z += p.z; r.w += p.w;
            }
            size_t off = (size_t)BB * AA * SS
                       + ((size_t)b * AA + a_lo + a2) * HH + 4 * hb;
            *(float4*)&out[off] = r;
        }
    }
}

extern "C" void kernel_launch(void* const* d_in, const int* in_sizes, int n_in,
                              void* d_out, int out_size) {
    const float* doc     = (const float*)d_in[0];  // (64,1024,128) f32
    const float* Wt      = (const float*)d_in[1];  // (8, 640) f32
    const float* aspProj = (const float*)d_in[2];  // (8,128,128) f32
    float* out = (float*)d_out;

    kc_kernel<<<80, 512>>>(aspProj, Wt);

    size_t sm1 = ((size_t)(CH2 + 4) * RSTRIDE + (size_t)AA * WW * HH + (size_t)AA * CH2)
               * sizeof(float);   // ~166 KB
    cudaFuncSetAttribute(k1_kernel, cudaFuncAttributeMaxDynamicSharedMemorySize, (int)sm1);
    k1_kernel<<<dim3(SS / CH2, BB), 256, sm1>>>(doc);

    k2_kernel<<<dim3(BB, 2), 1024>>>(doc, aspProj, out);
}